// round 5
// baseline (speedup 1.0000x reference)
#include <cuda_runtime.h>

#define NSEG 256
#define DDIM 256
#define TPB  256
#define MAXN 4096   // scratch capacity in proteins (N=2048 in this problem)

// Per-protein partial sums — overwritten every call, no zeroing required.
__device__ float4 g_partial[MAXN * (DDIM / 4)];   // [N][64] float4 = [N][256] float

// ---------------------------------------------------------------------------
// Kernel A: one block per protein. Each thread strides float4s of this
// protein's [L, D] slab (fully coalesced 128B transactions). Stride 256 over
// 64 float4s/row keeps each thread in column group (tid % 64); the
// cross-thread fold is a 4-way shared-memory sum, then threads 0..63 store
// the protein's 256-float partial-sum row (plain stores, no atomics).
__global__ void __launch_bounds__(TPB) pp_accum_kernel(
    const float4* __restrict__ in,       // [N, L*D/4]
    int vec_per_protein)                 // L*D/4
{
    __shared__ float4 sm[TPB];
    const int n   = blockIdx.x;
    const int tid = threadIdx.x;
    const float4* base = in + (size_t)n * (size_t)vec_per_protein;

    float4 acc = make_float4(0.f, 0.f, 0.f, 0.f);
    #pragma unroll 4
    for (int idx = tid; idx < vec_per_protein; idx += TPB) {
        float4 v = base[idx];
        acc.x += v.x; acc.y += v.y; acc.z += v.z; acc.w += v.w;
    }
    sm[tid] = acc;
    __syncthreads();

    if (tid < 64) {
        float4 a0 = sm[tid];
        float4 a1 = sm[tid + 64];
        float4 a2 = sm[tid + 128];
        float4 a3 = sm[tid + 192];
        float4 r;
        r.x = a0.x + a1.x + a2.x + a3.x;
        r.y = a0.y + a1.y + a2.y + a3.y;
        r.z = a0.z + a1.z + a2.z + a3.z;
        r.w = a0.w + a1.w + a2.w + a3.w;
        g_partial[n * (DDIM / 4) + tid] = r;
    }
}

// ---------------------------------------------------------------------------
// Kernel B: one block per segment. Keys are staged into SHARED memory
// (coalesced cooperative load), so the two binary searches run on 29-cycle
// LDS broadcasts instead of 234-cycle serially-dependent L2 hits. Thread t
// then sums column t of the matching partial rows (independent loads,
// unrolled for MLP) and writes out[b][t] = acc / ((hi-lo)*L).
//
// Key dtype detect (same trick as before, folded into the staging pass):
// viewing the buffer as int32 words, int64 values < 256 have all-zero odd
// words within the first nkeys words, while sorted int32 keys reach nonzero
// values at odd indices.
__global__ void __launch_bounds__(TPB) pp_gather_kernel(
    const int* __restrict__ kwords,      // keys viewed as int32 words
    float* __restrict__ out,             // [NSEG, DDIM]
    int nkeys, float Lf)
{
    __shared__ int skey[MAXN];
    const int b   = blockIdx.x;
    const int tid = threadIdx.x;

    // dtype detect over the first nkeys words (valid for both layouts)
    int local = 0;
    for (int k = tid; k < nkeys; k += TPB)
        if ((k & 1) && kwords[k] != 0) local = 1;
    const int is32 = __syncthreads_or(local);

    // stage keys into shared (int64 path reads lo words; values < 2^31)
    if (is32) {
        for (int n = tid; n < nkeys; n += TPB) skey[n] = kwords[n];
    } else {
        for (int n = tid; n < nkeys; n += TPB) skey[n] = kwords[2 * n];
    }
    __syncthreads();

    // lower_bound(b) and lower_bound(b+1) on shared keys — uniform across
    // the block, LDS broadcast each step.
    int lo, hi;
    {
        int l = 0, r = nkeys;
        while (l < r) { int m = (l + r) >> 1; if (skey[m] < b) l = m + 1; else r = m; }
        lo = l;
        l = lo; r = nkeys;
        while (l < r) { int m = (l + r) >> 1; if (skey[m] < b + 1) l = m + 1; else r = m; }
        hi = l;
    }

    // column sum: independent, coalesced loads; unrolled for MLP
    const float* part = (const float*)g_partial;
    float acc = 0.0f;
    int n = lo;
    #pragma unroll 4
    for (; n + 4 <= hi; n += 4) {
        float a0 = part[(n + 0) * DDIM + tid];
        float a1 = part[(n + 1) * DDIM + tid];
        float a2 = part[(n + 2) * DDIM + tid];
        float a3 = part[(n + 3) * DDIM + tid];
        acc += (a0 + a1) + (a2 + a3);
    }
    for (; n < hi; ++n) acc += part[n * DDIM + tid];

    const int cnt = (hi > lo) ? (hi - lo) : 1;   // segments guaranteed non-empty
    out[b * DDIM + tid] = acc / ((float)cnt * Lf);
}

// ---------------------------------------------------------------------------
extern "C" void kernel_launch(void* const* d_in, const int* in_sizes, int n_in,
                              void* d_out, int out_size) {
    // Pick embeds by element count (defend against input-order surprises).
    int ei = 0, ki = 1;
    if (n_in >= 2 && in_sizes[1] > in_sizes[0]) { ei = 1; ki = 0; }

    const float* embeds = (const float*)d_in[ei];   // [N, L, D] fp32
    const int*   kwords = (const int*)d_in[ki];     // [N] int32 or int64 (as words)

    const int N            = in_sizes[ki];
    const int per_protein  = in_sizes[ei] / N;      // L * D
    const int L            = per_protein / DDIM;    // sequence length
    const int vec_per_prot = per_protein / 4;

    pp_accum_kernel<<<N, TPB>>>((const float4*)embeds, vec_per_prot);
    pp_gather_kernel<<<NSEG, TPB>>>(kwords, (float*)d_out, N, (float)L);
}

// round 6
// speedup vs baseline: 1.0431x; 1.0431x over previous
#include <cuda_runtime.h>

#define NSEG 256
#define DDIM 256
#define TPB  256
#define MAXN 4096   // key scratch capacity (N=2048 here)

// Written by pre-kernel block 0 each call (no zero-init needed — overwritten).
__device__ int   g_keys[MAXN];    // keys converted to int32
__device__ float g_scale[NSEG];   // 1 / (count_b * L)

// ---------------------------------------------------------------------------
// Kernel A: zero d_out (poisoned by harness); block 0 additionally converts
// keys and builds the per-segment scale table.
//
// Key dtype detect: viewing the buffer as int32 words, int64 values < 256
// have all-zero odd words within the first nkeys words, while sorted int32
// keys reach nonzero values at odd indices.
__global__ void __launch_bounds__(TPB) pp_pre_kernel(
    const int* __restrict__ kwords,    // keys viewed as int32 words
    float4* __restrict__ out4,         // d_out as float4
    int nout4, int nkeys, float Lf)
{
    int i = blockIdx.x * blockDim.x + threadIdx.x;
    if (i < nout4) out4[i] = make_float4(0.f, 0.f, 0.f, 0.f);

    if (blockIdx.x == 0) {
        const int tid = threadIdx.x;
        __shared__ int hist[NSEG];
        hist[tid] = 0;

        // dtype detect
        int local = 0;
        for (int k = tid; k < nkeys; k += TPB)
            if ((k & 1) && kwords[k] != 0) local = 1;
        const int is32 = __syncthreads_or(local);

        // convert keys + histogram counts (smem atomics)
        for (int n = tid; n < nkeys; n += TPB) {
            int key = is32 ? kwords[n] : kwords[2 * n];   // int64 lo word
            key &= (NSEG - 1);                            // never OOB
            g_keys[n] = key;
            atomicAdd(&hist[key], 1);
        }
        __syncthreads();

        int c = hist[tid];
        g_scale[tid] = __fdividef(1.0f, (float)(c > 0 ? c : 1) * Lf);
    }
}

// ---------------------------------------------------------------------------
// Kernel B: one block per protein. Each thread strides float4s of this
// protein's [L, D] slab (fully coalesced 128B transactions). Stride 256 over
// 64 float4s/row keeps each thread in column group (tid % 64); cross-thread
// fold is a 4-way shared-memory sum, then threads 0..63 atomicAdd the
// pre-scaled partials straight into d_out (524K REDGs over 64K addresses).
// b/scale are loaded before the stream loop so their latency hides fully.
__global__ void __launch_bounds__(TPB) pp_accum_kernel(
    const float4* __restrict__ in,       // [N, L*D/4]
    float* __restrict__ out,             // [NSEG, DDIM]
    int vec_per_protein)                 // L*D/4
{
    __shared__ float4 sm[TPB];
    const int n   = blockIdx.x;
    const int tid = threadIdx.x;

    // uniform per-block metadata — issue early, hidden under the stream
    const int   b     = g_keys[n];
    const float scale = g_scale[b];

    const float4* base = in + (size_t)n * (size_t)vec_per_protein;
    float4 acc = make_float4(0.f, 0.f, 0.f, 0.f);
    #pragma unroll 4
    for (int idx = tid; idx < vec_per_protein; idx += TPB) {
        float4 v = base[idx];
        acc.x += v.x; acc.y += v.y; acc.z += v.z; acc.w += v.w;
    }
    sm[tid] = acc;
    __syncthreads();

    if (tid < 64) {
        float4 a0 = sm[tid];
        float4 a1 = sm[tid + 64];
        float4 a2 = sm[tid + 128];
        float4 a3 = sm[tid + 192];
        float* dst = out + b * DDIM + tid * 4;
        atomicAdd(dst + 0, (a0.x + a1.x + a2.x + a3.x) * scale);
        atomicAdd(dst + 1, (a0.y + a1.y + a2.y + a3.y) * scale);
        atomicAdd(dst + 2, (a0.z + a1.z + a2.z + a3.z) * scale);
        atomicAdd(dst + 3, (a0.w + a1.w + a2.w + a3.w) * scale);
    }
}

// ---------------------------------------------------------------------------
extern "C" void kernel_launch(void* const* d_in, const int* in_sizes, int n_in,
                              void* d_out, int out_size) {
    // Pick embeds by element count (defend against input-order surprises).
    int ei = 0, ki = 1;
    if (n_in >= 2 && in_sizes[1] > in_sizes[0]) { ei = 1; ki = 0; }

    const float* embeds = (const float*)d_in[ei];   // [N, L, D] fp32
    const int*   kwords = (const int*)d_in[ki];     // [N] int32 or int64 (words)

    const int N            = in_sizes[ki];
    const int per_protein  = in_sizes[ei] / N;      // L * D
    const int L            = per_protein / DDIM;    // sequence length
    const int vec_per_prot = per_protein / 4;
    const int nout4        = out_size / 4;

    pp_pre_kernel<<<(nout4 + TPB - 1) / TPB, TPB>>>(
        kwords, (float4*)d_out, nout4, N, (float)L);
    pp_accum_kernel<<<N, TPB>>>((const float4*)embeds, (float*)d_out,
                                vec_per_prot);
}